// round 4
// baseline (speedup 1.0000x reference)
#include <cuda_runtime.h>
#include <math.h>

// Problem constants
#define B_SZ 4
#define T_SZ 64
#define N_SZ 128
#define HEADS 32
#define HK 32
#define D_DIM 1024              // HEADS*HK
#define K2 2048                 // 2*D
#define M_TOTAL (B_SZ * T_SZ * N_SZ)   // 32768 rows
#define MD ((size_t)M_TOTAL * D_DIM)   // 33,554,432 elements per buffer

// Single consolidated scratch buffer (allocation-free rule: __device__ global).
// Layout: [q | k | v | ao], each MD floats.
__device__ float g_scratch[4 * MD];

// ---------------------------------------------------------------------------
// Tiled SGEMM: C[M,N] = relu(A[M,K] @ W[K,N] + bias)
// SPLIT=1: A is the concat [A0 | A1], each M x (K/2) row-major; blockIdx.z
// selects among up to 3 (W, bias, C) triples (fused QKV).
// 128x128 tile, BK=16, 256 threads, 8x8 per-thread register tile.
// ---------------------------------------------------------------------------
template <int SPLIT>
__global__ void __launch_bounds__(256) gemm_bias_relu(
    const float* __restrict__ A0, const float* __restrict__ A1,
    const float* __restrict__ W0, const float* __restrict__ b0_,
    float* __restrict__ C0,
    const float* __restrict__ W1, const float* __restrict__ b1_,
    float* __restrict__ C1,
    const float* __restrict__ W2, const float* __restrict__ b2_,
    float* __restrict__ C2,
    int M, int N, int K)
{
    __shared__ float As[16][132];   // stored transposed: As[k][m], pad to 132
    __shared__ float Bs[16][128];

    const float* W    = (blockIdx.z == 0) ? W0  : (blockIdx.z == 1) ? W1  : W2;
    const float* bias = (blockIdx.z == 0) ? b0_ : (blockIdx.z == 1) ? b1_ : b2_;
    float*       C    = (blockIdx.z == 0) ? C0  : (blockIdx.z == 1) ? C1  : C2;

    const int bn = blockIdx.x;
    const int bm = blockIdx.y;
    const int tid = threadIdx.x;
    const int tx = tid & 15;        // 0..15  -> col group
    const int ty = tid >> 4;        // 0..15  -> row group
    const int rowBase = bm * 128;
    const int colBase = bn * 128;
    const int Kh = K >> 1;

    float acc[8][8];
    #pragma unroll
    for (int i = 0; i < 8; i++)
        #pragma unroll
        for (int j = 0; j < 8; j++) acc[i][j] = 0.f;

    for (int k0 = 0; k0 < K; k0 += 16) {
        // --- load A tile (128 rows x 16 k) as float4, store transposed ---
        #pragma unroll
        for (int l = 0; l < 2; l++) {
            int idx = tid * 2 + l;          // 0..511
            int r   = idx >> 2;             // 0..127
            int c4  = (idx & 3) * 4;        // 0,4,8,12
            int kk  = k0 + c4;
            const float* src;
            if (SPLIT) {
                if (kk < Kh) src = A0 + (size_t)(rowBase + r) * Kh + kk;
                else         src = A1 + (size_t)(rowBase + r) * Kh + (kk - Kh);
            } else {
                src = A0 + (size_t)(rowBase + r) * K + kk;
            }
            float4 av = *reinterpret_cast<const float4*>(src);
            As[c4 + 0][r] = av.x;
            As[c4 + 1][r] = av.y;
            As[c4 + 2][r] = av.z;
            As[c4 + 3][r] = av.w;
        }
        // --- load W tile (16 k x 128 cols) ---
        #pragma unroll
        for (int l = 0; l < 2; l++) {
            int idx = tid * 2 + l;          // 0..511
            int r   = idx >> 5;             // 0..15
            int c4  = (idx & 31) * 4;       // 0..124
            float4 bv = *reinterpret_cast<const float4*>(
                W + (size_t)(k0 + r) * N + colBase + c4);
            *reinterpret_cast<float4*>(&Bs[r][c4]) = bv;
        }
        __syncthreads();

        #pragma unroll
        for (int kk = 0; kk < 16; kk++) {
            float a[8], b[8];
            #pragma unroll
            for (int i = 0; i < 8; i++) a[i] = As[kk][ty * 8 + i];
            #pragma unroll
            for (int j = 0; j < 8; j++) b[j] = Bs[kk][tx * 8 + j];
            #pragma unroll
            for (int i = 0; i < 8; i++)
                #pragma unroll
                for (int j = 0; j < 8; j++)
                    acc[i][j] = fmaf(a[i], b[j], acc[i][j]);
        }
        __syncthreads();
    }

    // --- epilogue: bias + relu, vectorized stores ---
    #pragma unroll
    for (int i = 0; i < 8; i++) {
        int r = rowBase + ty * 8 + i;
        #pragma unroll
        for (int j = 0; j < 8; j += 4) {
            int c = colBase + tx * 8 + j;
            float4 o;
            o.x = fmaxf(acc[i][j + 0] + bias[c + 0], 0.f);
            o.y = fmaxf(acc[i][j + 1] + bias[c + 1], 0.f);
            o.z = fmaxf(acc[i][j + 2] + bias[c + 2], 0.f);
            o.w = fmaxf(acc[i][j + 3] + bias[c + 3], 0.f);
            *reinterpret_cast<float4*>(C + (size_t)r * N + c) = o;
        }
    }
}

// ---------------------------------------------------------------------------
// Causal attention over time per (b, n, head). One 128-thread block per
// (b,n,h). T=64, head_dim=32. q/k/v layout: row (b,t,n) of D=1024, head h at
// offset h*32.
// ---------------------------------------------------------------------------
__global__ void __launch_bounds__(128) attn_kernel(
    const float* __restrict__ Q, const float* __restrict__ Kk,
    const float* __restrict__ V, float* __restrict__ O)
{
    __shared__ float qs[64][33];
    __shared__ float ks[64][33];
    __shared__ float vs[64][33];
    __shared__ float ps[64][65];

    const int bid = blockIdx.x;           // 0..16383
    const int h = bid & 31;
    const int n = (bid >> 5) & 127;
    const int b = bid >> 12;
    const int tid = threadIdx.x;
    const int lane = tid & 31;
    const int warp = tid >> 5;

    const size_t strideT = (size_t)N_SZ * D_DIM;          // 131072
    const size_t base = (((size_t)b * T_SZ) * N_SZ + n) * D_DIM + (size_t)h * HK;

    // load q/k/v tiles: warp w handles rows [w*16, w*16+16)
    #pragma unroll
    for (int i = 0; i < 16; i++) {
        int t = warp * 16 + i;
        size_t off = base + (size_t)t * strideT + lane;
        qs[t][lane] = Q[off];
        ks[t][lane] = Kk[off];
        vs[t][lane] = V[off];
    }
    __syncthreads();

    // scores (only s <= t)
    const float scale = 0.17677669529663687f;   // 1/sqrt(32)
    #pragma unroll 1
    for (int i = 0; i < 32; i++) {
        int idx = i * 128 + tid;      // warp-uniform t
        int t = idx >> 6;
        int s = idx & 63;
        if (s <= t) {
            float acc = 0.f;
            #pragma unroll
            for (int kk = 0; kk < 32; kk++)
                acc = fmaf(qs[t][kk], ks[s][kk], acc);
            ps[t][s] = acc * scale;
        }
    }
    __syncthreads();

    // softmax per row (causal; masked entries are exactly 0 in the reference
    // since exp(-32767 - m) underflows to 0 in fp32)
    #pragma unroll 1
    for (int i = 0; i < 16; i++) {
        int t = warp * 16 + i;
        float x0 = (lane <= t) ? ps[t][lane] : -1e30f;
        float x1 = (lane + 32 <= t) ? ps[t][lane + 32] : -1e30f;
        float m = fmaxf(x0, x1);
        #pragma unroll
        for (int o = 16; o; o >>= 1) m = fmaxf(m, __shfl_xor_sync(0xffffffffu, m, o));
        float e0 = (lane <= t) ? expf(x0 - m) : 0.f;
        float e1 = (lane + 32 <= t) ? expf(x1 - m) : 0.f;
        float sum = e0 + e1;
        #pragma unroll
        for (int o = 16; o; o >>= 1) sum += __shfl_xor_sync(0xffffffffu, sum, o);
        float inv = 1.f / sum;
        ps[t][lane] = e0 * inv;
        ps[t][lane + 32] = e1 * inv;
    }
    __syncthreads();

    // out[t][kk] = sum_{s<=t} p[t][s] * v[s][kk]; kk = lane, t warp-uniform
    #pragma unroll 1
    for (int i = 0; i < 16; i++) {
        int t = warp + 4 * i;
        float acc = 0.f;
        for (int s = 0; s <= t; s++)
            acc = fmaf(ps[t][s], vs[s][lane], acc);
        O[base + (size_t)t * strideT + lane] = acc;
    }
}

// ---------------------------------------------------------------------------
extern "C" void kernel_launch(void* const* d_in, const int* in_sizes, int n_in,
                              void* d_out, int out_size)
{
    const float* X   = (const float*)d_in[0];
    const float* STE = (const float*)d_in[1];
    const float* Wq  = (const float*)d_in[2];
    const float* bq  = (const float*)d_in[3];
    const float* Wk  = (const float*)d_in[4];
    const float* bk  = (const float*)d_in[5];
    const float* Wv  = (const float*)d_in[6];
    const float* bv  = (const float*)d_in[7];
    const float* Wo  = (const float*)d_in[8];
    const float* bo  = (const float*)d_in[9];
    float* out = (float*)d_out;

    float* scratch = nullptr;
    cudaGetSymbolAddress((void**)&scratch, g_scratch);
    float* q  = scratch;
    float* k  = scratch + MD;
    float* v  = scratch + 2 * MD;
    float* ao = scratch + 3 * MD;

    dim3 block(256);
    dim3 gridQKV(D_DIM / 128, M_TOTAL / 128, 3);   // (8, 256, 3)
    dim3 gridO(D_DIM / 128, M_TOTAL / 128, 1);

    // Fused QKV projections: relu([X|STE] @ W{q,k,v} + b{q,k,v})
    gemm_bias_relu<1><<<gridQKV, block>>>(X, STE,
                                          Wq, bq, q,
                                          Wk, bk, k,
                                          Wv, bv, v,
                                          M_TOTAL, D_DIM, K2);

    // Causal temporal attention per (b, n, head)
    attn_kernel<<<B_SZ * N_SZ * HEADS, 128>>>(q, k, v, ao);

    // Output projection: relu(ao @ Wo + bo)
    gemm_bias_relu<0><<<gridO, block>>>(ao, nullptr,
                                        Wo, bo, out,
                                        Wo, bo, out,
                                        Wo, bo, out,
                                        M_TOTAL, D_DIM, D_DIM);
}

// round 6
// speedup vs baseline: 2.0900x; 2.0900x over previous
#include <cuda_runtime.h>
#include <cuda_bf16.h>
#include <math.h>
#include <stdint.h>

// ---------------------------------------------------------------------------
// Problem constants
// ---------------------------------------------------------------------------
#define B_SZ 4
#define T_SZ 64
#define N_SZ 128
#define HEADS 32
#define D_DIM 1024
#define K2 2048
#define M_TOTAL 32768              // B*T*N
#define NEFF 3072                  // fused QKV output cols

// ---------------------------------------------------------------------------
// Scratch carve-out (single __device__ blob; allocation-free rule)
// ---------------------------------------------------------------------------
#define OFF_QKV   ((size_t)0)                       // fp32 [32768,3072]
#define OFF_AO    (OFF_QKV  + (size_t)402653184)    // fp32 [32768,1024]
#define OFF_AHI   (OFF_AO   + (size_t)134217728)    // bf16 [32768,2048]
#define OFF_ALO   (OFF_AHI  + (size_t)134217728)
#define OFF_AOHI  (OFF_ALO  + (size_t)134217728)    // bf16 [32768,1024]
#define OFF_AOLO  (OFF_AOHI + (size_t)67108864)
#define OFF_WTHI  (OFF_AOLO + (size_t)67108864)     // bf16 [3072,2048]
#define OFF_WTLO  (OFF_WTHI + (size_t)12582912)
#define OFF_WOTHI (OFF_WTLO + (size_t)12582912)     // bf16 [1024,1024]
#define OFF_WOTLO (OFF_WOTHI + (size_t)2097152)
#define OFF_BIAS  (OFF_WOTLO + (size_t)2097152)     // fp32 [3072]
#define SCRATCH_BYTES (OFF_BIAS + (size_t)12288)

__device__ __align__(1024) unsigned char g_scratch[SCRATCH_BYTES];

// ---------------------------------------------------------------------------
// PTX helpers available on base sm_100 (no 'a' features)
// ---------------------------------------------------------------------------
static __device__ __forceinline__ unsigned smem_u32(const void* p) {
    unsigned r;
    asm("{ .reg .u64 t; cvta.to.shared.u64 t, %1; cvt.u32.u64 %0, t; }"
        : "=r"(r) : "l"(p));
    return r;
}
static __device__ __forceinline__ void cp16(void* dst, const void* src) {
    unsigned d = smem_u32(dst);
    asm volatile("cp.async.cg.shared.global [%0], [%1], 16;"
                 :: "r"(d), "l"(src) : "memory");
}
static __device__ __forceinline__ void cp_commit() {
    asm volatile("cp.async.commit_group;" ::: "memory");
}
static __device__ __forceinline__ void cp_wait0() {
    asm volatile("cp.async.wait_group 0;" ::: "memory");
}
static __device__ __forceinline__ void ldmx4(
    unsigned& r0, unsigned& r1, unsigned& r2, unsigned& r3, unsigned addr) {
    asm volatile("ldmatrix.sync.aligned.m8n8.x4.shared.b16 {%0,%1,%2,%3}, [%4];"
                 : "=r"(r0), "=r"(r1), "=r"(r2), "=r"(r3) : "r"(addr));
}
static __device__ __forceinline__ void mma16816(
    float* c, const unsigned* a, unsigned b0, unsigned b1) {
    asm volatile(
        "mma.sync.aligned.m16n8k16.row.col.f32.bf16.bf16.f32 "
        "{%0,%1,%2,%3}, {%4,%5,%6,%7}, {%8,%9}, {%0,%1,%2,%3};"
        : "+f"(c[0]), "+f"(c[1]), "+f"(c[2]), "+f"(c[3])
        : "r"(a[0]), "r"(a[1]), "r"(a[2]), "r"(a[3]), "r"(b0), "r"(b1));
}

// ---------------------------------------------------------------------------
// bf16 split-precision GEMM via mma.sync (HMMA path; sm_100-base legal).
// C[M, cstride-window] = relu( A @ WT^T + bias ); A fp32 split (Ahi,Alo),
// W^T split (WThi, WTlo); K_eff = 3K: regions (hi,hi),(hi,lo),(lo,hi).
// CTA tile 128x128, BK=32, 8 warps (warptile 64x32), 2-stage cp.async.
// ---------------------------------------------------------------------------
#define PADK 40                    // padded halves per smem row (80B stride)

__global__ void __launch_bounds__(256, 2) mma_gemm(
    const __nv_bfloat16* __restrict__ Ahi,
    const __nv_bfloat16* __restrict__ Alo,
    const __nv_bfloat16* __restrict__ WThi,
    const __nv_bfloat16* __restrict__ WTlo,
    const float* __restrict__ bias,
    float* __restrict__ C,
    int K, int cstride)
{
    __shared__ __align__(16) __nv_bfloat16 sA[2][128 * PADK];
    __shared__ __align__(16) __nv_bfloat16 sB[2][128 * PADK];

    const int tid  = threadIdx.x;
    const int lane = tid & 31;
    const int warp = tid >> 5;
    const int wm   = warp >> 2;         // 0..1
    const int wn   = warp & 3;          // 0..3
    const int tileM = blockIdx.y * 128;
    const int tileN = blockIdx.x * 128;

    const int CPR = K >> 5;             // 32-wide K chunks per region
    const int NC  = 3 * CPR;

    float acc[4][4][4];
    #pragma unroll
    for (int mi = 0; mi < 4; mi++)
        #pragma unroll
        for (int ni = 0; ni < 4; ni++)
            #pragma unroll
            for (int e = 0; e < 4; e++) acc[mi][ni][e] = 0.f;

    // stage copy: chunk kc -> stage s
    auto do_copy = [&](int kc, int s) {
        const int region = kc / CPR;
        const int klocal = (kc % CPR) << 5;
        const __nv_bfloat16* Asrc = (region < 2) ? Ahi : Alo;
        const __nv_bfloat16* Bsrc = (region == 1) ? WTlo : WThi;
        #pragma unroll
        for (int i = 0; i < 2; i++) {
            int idx = tid + i * 256;            // 0..511
            int r = idx >> 2, c = idx & 3;
            cp16(&sA[s][r * PADK + c * 8],
                 Asrc + (size_t)(tileM + r) * K + klocal + c * 8);
        }
        #pragma unroll
        for (int i = 0; i < 2; i++) {
            int idx = tid + i * 256;
            int r = idx >> 2, c = idx & 3;
            cp16(&sB[s][r * PADK + c * 8],
                 Bsrc + (size_t)(tileN + r) * K + klocal + c * 8);
        }
    };

    do_copy(0, 0);
    cp_commit();

    for (int kc = 0; kc < NC; kc++) {
        const int s = kc & 1;
        cp_wait0();
        __syncthreads();
        if (kc + 1 < NC) do_copy(kc + 1, s ^ 1);
        cp_commit();

        // compute on stage s: two k16 steps
        #pragma unroll
        for (int ks = 0; ks < 2; ks++) {
            unsigned a[4][4];
            #pragma unroll
            for (int mi = 0; mi < 4; mi++) {
                int row = wm * 64 + mi * 16 + (lane & 15);
                int kb  = ks * 16 + (lane >> 4) * 8;
                ldmx4(a[mi][0], a[mi][1], a[mi][2], a[mi][3],
                      smem_u32(&sA[s][row * PADK + kb]));
            }
            unsigned b[4][2];
            #pragma unroll
            for (int ng = 0; ng < 2; ng++) {
                int row = wn * 32 + ng * 16 + ((lane >> 4) << 3) + (lane & 7);
                int kb  = ks * 16 + ((lane >> 3) & 1) * 8;
                unsigned r0, r1, r2, r3;
                ldmx4(r0, r1, r2, r3, smem_u32(&sB[s][row * PADK + kb]));
                b[ng * 2][0] = r0;  b[ng * 2][1] = r1;
                b[ng * 2 + 1][0] = r2;  b[ng * 2 + 1][1] = r3;
            }
            #pragma unroll
            for (int mi = 0; mi < 4; mi++)
                #pragma unroll
                for (int ni = 0; ni < 4; ni++)
                    mma16816(acc[mi][ni], a[mi], b[ni][0], b[ni][1]);
        }
    }

    // epilogue: bias + relu
    #pragma unroll
    for (int mi = 0; mi < 4; mi++) {
        int r0 = tileM + wm * 64 + mi * 16 + (lane >> 2);
        #pragma unroll
        for (int ni = 0; ni < 4; ni++) {
            int c = tileN + wn * 32 + ni * 8 + 2 * (lane & 3);
            float b0 = bias[c], b1 = bias[c + 1];
            float2 v0, v1;
            v0.x = fmaxf(acc[mi][ni][0] + b0, 0.f);
            v0.y = fmaxf(acc[mi][ni][1] + b1, 0.f);
            v1.x = fmaxf(acc[mi][ni][2] + b0, 0.f);
            v1.y = fmaxf(acc[mi][ni][3] + b1, 0.f);
            *reinterpret_cast<float2*>(C + (size_t)r0 * cstride + c) = v0;
            *reinterpret_cast<float2*>(C + (size_t)(r0 + 8) * cstride + c) = v1;
        }
    }
}

// ---------------------------------------------------------------------------
// Prep kernels
// ---------------------------------------------------------------------------
__global__ void __launch_bounds__(256) prep_a(
    const float* __restrict__ X, const float* __restrict__ STE,
    __nv_bfloat16* __restrict__ Ahi, __nv_bfloat16* __restrict__ Alo)
{
    size_t idx = (size_t)blockIdx.x * 256 + threadIdx.x;   // one float4
    size_t row = idx >> 9;
    int    c4  = (int)(idx & 511) * 4;
    const float4 v = (c4 < 1024)
        ? *reinterpret_cast<const float4*>(X + row * 1024 + c4)
        : *reinterpret_cast<const float4*>(STE + row * 1024 + (c4 - 1024));
    const float xs[4] = {v.x, v.y, v.z, v.w};
    ushort4 hv, lv;
    unsigned short* hp = &hv.x;
    unsigned short* lp = &lv.x;
    #pragma unroll
    for (int i = 0; i < 4; i++) {
        __nv_bfloat16 h = __float2bfloat16_rn(xs[i]);
        __nv_bfloat16 l = __float2bfloat16_rn(xs[i] - __bfloat162float(h));
        hp[i] = __bfloat16_as_ushort(h);
        lp[i] = __bfloat16_as_ushort(l);
    }
    *reinterpret_cast<ushort4*>(Ahi + row * 2048 + c4) = hv;
    *reinterpret_cast<ushort4*>(Alo + row * 2048 + c4) = lv;
}

__global__ void __launch_bounds__(256) prep_ao(
    const float* __restrict__ AO,
    __nv_bfloat16* __restrict__ Hi, __nv_bfloat16* __restrict__ Lo)
{
    size_t idx = (size_t)blockIdx.x * 256 + threadIdx.x;   // one float4
    const float4 v = *reinterpret_cast<const float4*>(AO + idx * 4);
    const float xs[4] = {v.x, v.y, v.z, v.w};
    ushort4 hv, lv;
    unsigned short* hp = &hv.x;
    unsigned short* lp = &lv.x;
    #pragma unroll
    for (int i = 0; i < 4; i++) {
        __nv_bfloat16 h = __float2bfloat16_rn(xs[i]);
        __nv_bfloat16 l = __float2bfloat16_rn(xs[i] - __bfloat162float(h));
        hp[i] = __bfloat16_as_ushort(h);
        lp[i] = __bfloat16_as_ushort(l);
    }
    *reinterpret_cast<ushort4*>(Hi + idx * 4) = hv;
    *reinterpret_cast<ushort4*>(Lo + idx * 4) = lv;
}

// W [K,1024] fp32 -> WT hi/lo bf16 [1024, K]  (grid: (K/32, 32), block 32x8)
__global__ void __launch_bounds__(256) prep_wt(
    const float* __restrict__ W,
    __nv_bfloat16* __restrict__ Thi, __nv_bfloat16* __restrict__ Tlo, int K)
{
    __shared__ float t[32][33];
    const int kb = blockIdx.x * 32, nb = blockIdx.y * 32;
    const int x = threadIdx.x, y = threadIdx.y;
    #pragma unroll
    for (int i = 0; i < 32; i += 8)
        t[y + i][x] = W[(size_t)(kb + y + i) * 1024 + nb + x];
    __syncthreads();
    #pragma unroll
    for (int i = 0; i < 32; i += 8) {
        float v = t[x][y + i];
        __nv_bfloat16 h = __float2bfloat16_rn(v);
        __nv_bfloat16 l = __float2bfloat16_rn(v - __bfloat162float(h));
        size_t o = (size_t)(nb + y + i) * K + kb + x;
        Thi[o] = h;
        Tlo[o] = l;
    }
}

__global__ void __launch_bounds__(256) fuse_bias(
    const float* __restrict__ bq, const float* __restrict__ bk,
    const float* __restrict__ bv, float* __restrict__ out)
{
    int i = blockIdx.x * 256 + threadIdx.x;
    if (i < 3072)
        out[i] = (i < 1024) ? bq[i] : (i < 2048) ? bk[i - 1024] : bv[i - 2048];
}

// ---------------------------------------------------------------------------
// Causal attention per (b, n, head); qkv fused [32768, 3072] fp32.
// ---------------------------------------------------------------------------
__global__ void __launch_bounds__(128) attn_kernel(
    const float* __restrict__ QKV, float* __restrict__ O)
{
    __shared__ float qs[64][33];
    __shared__ float ks[64][33];
    __shared__ float vs[64][33];
    __shared__ float ps[64][65];

    const int bid = blockIdx.x;
    const int h = bid & 31;
    const int n = (bid >> 5) & 127;
    const int b = bid >> 12;
    const int tid = threadIdx.x;
    const int lane = tid & 31;
    const int warp = tid >> 5;

    const int hc = h * 32 + lane;

    #pragma unroll
    for (int i = 0; i < 16; i++) {
        int t = warp * 16 + i;
        size_t row = ((size_t)b * 64 + t) * 128 + n;
        const float* r = QKV + row * 3072;
        qs[t][lane] = r[hc];
        ks[t][lane] = r[1024 + hc];
        vs[t][lane] = r[2048 + hc];
    }
    __syncthreads();

    const float scale = 0.17677669529663687f;  // 1/sqrt(32)
    #pragma unroll 1
    for (int i = 0; i < 32; i++) {
        int idx = i * 128 + tid;
        int t = idx >> 6;
        int s = idx & 63;
        if (s <= t) {
            float acc = 0.f;
            #pragma unroll
            for (int kk = 0; kk < 32; kk++)
                acc = fmaf(qs[t][kk], ks[s][kk], acc);
            ps[t][s] = acc * scale;
        }
    }
    __syncthreads();

    #pragma unroll 1
    for (int i = 0; i < 16; i++) {
        int t = warp * 16 + i;
        float x0 = (lane <= t) ? ps[t][lane] : -1e30f;
        float x1 = (lane + 32 <= t) ? ps[t][lane + 32] : -1e30f;
        float m = fmaxf(x0, x1);
        #pragma unroll
        for (int o = 16; o; o >>= 1) m = fmaxf(m, __shfl_xor_sync(0xffffffffu, m, o));
        float e0 = (lane <= t) ? expf(x0 - m) : 0.f;
        float e1 = (lane + 32 <= t) ? expf(x1 - m) : 0.f;
        float sum = e0 + e1;
        #pragma unroll
        for (int o = 16; o; o >>= 1) sum += __shfl_xor_sync(0xffffffffu, sum, o);
        float inv = 1.f / sum;
        ps[t][lane] = e0 * inv;
        ps[t][lane + 32] = e1 * inv;
    }
    __syncthreads();

    #pragma unroll 1
    for (int i = 0; i < 16; i++) {
        int t = warp + 4 * i;
        float acc = 0.f;
        for (int s = 0; s <= t; s++)
            acc = fmaf(ps[t][s], vs[s][lane], acc);
        size_t row = ((size_t)b * 64 + t) * 128 + n;
        O[row * 1024 + hc] = acc;
    }
}

// ---------------------------------------------------------------------------
extern "C" void kernel_launch(void* const* d_in, const int* in_sizes, int n_in,
                              void* d_out, int out_size)
{
    const float* X   = (const float*)d_in[0];
    const float* STE = (const float*)d_in[1];
    const float* Wq  = (const float*)d_in[2];
    const float* bq  = (const float*)d_in[3];
    const float* Wk  = (const float*)d_in[4];
    const float* bk  = (const float*)d_in[5];
    const float* Wv  = (const float*)d_in[6];
    const float* bv  = (const float*)d_in[7];
    const float* Wo  = (const float*)d_in[8];
    const float* bo  = (const float*)d_in[9];
    float* out = (float*)d_out;

    unsigned char* sc = nullptr;
    cudaGetSymbolAddress((void**)&sc, g_scratch);
    float*         qkv   = (float*)(sc + OFF_QKV);
    float*         ao    = (float*)(sc + OFF_AO);
    __nv_bfloat16* Ahi   = (__nv_bfloat16*)(sc + OFF_AHI);
    __nv_bfloat16* Alo   = (__nv_bfloat16*)(sc + OFF_ALO);
    __nv_bfloat16* AOhi  = (__nv_bfloat16*)(sc + OFF_AOHI);
    __nv_bfloat16* AOlo  = (__nv_bfloat16*)(sc + OFF_AOLO);
    __nv_bfloat16* WThi  = (__nv_bfloat16*)(sc + OFF_WTHI);
    __nv_bfloat16* WTlo  = (__nv_bfloat16*)(sc + OFF_WTLO);
    __nv_bfloat16* WOThi = (__nv_bfloat16*)(sc + OFF_WOTHI);
    __nv_bfloat16* WOTlo = (__nv_bfloat16*)(sc + OFF_WOTLO);
    float*         biasF = (float*)(sc + OFF_BIAS);

    // --- prep: split inputs and weights into bf16 hi/lo ---
    prep_a<<<65536, 256>>>(X, STE, Ahi, Alo);
    dim3 tb(32, 8);
    prep_wt<<<dim3(64, 32), tb>>>(Wq, WThi,             WTlo,             K2);
    prep_wt<<<dim3(64, 32), tb>>>(Wk, WThi + 1024 * K2, WTlo + 1024 * K2, K2);
    prep_wt<<<dim3(64, 32), tb>>>(Wv, WThi + 2048 * K2, WTlo + 2048 * K2, K2);
    prep_wt<<<dim3(32, 32), tb>>>(Wo, WOThi, WOTlo, D_DIM);
    fuse_bias<<<12, 256>>>(bq, bk, bv, biasF);

    // --- fused QKV projection: qkv = relu([X|STE] @ [Wq|Wk|Wv] + b) ---
    mma_gemm<<<dim3(NEFF / 128, M_TOTAL / 128), 256>>>(
        Ahi, Alo, WThi, WTlo, biasF, qkv, K2, NEFF);

    // --- causal temporal attention ---
    attn_kernel<<<B_SZ * N_SZ * HEADS, 128>>>(qkv, ao);

    // --- output projection: out = relu(ao @ Wo + bo) ---
    prep_ao<<<32768, 256>>>(ao, AOhi, AOlo);
    mma_gemm<<<dim3(D_DIM / 128, M_TOTAL / 128), 256>>>(
        AOhi, AOlo, WOThi, WOTlo, bo, out, D_DIM, D_DIM);
}